// round 8
// baseline (speedup 1.0000x reference)
#include <cuda_runtime.h>
#include <math.h>

#define RNK 8
#define DIM 2048
#define BSZ 8
#define SEQ 2048
#define ROWS_PER_BLOCK 64
#define ROWS_PER_WARP 4
#define NBLOCKS 256
#define SCALING 2.0f   /* 16 / r */

typedef unsigned long long ull;

__device__ __forceinline__ void fma2(ull& acc, ull a, ull b) {
    asm("fma.rn.f32x2 %0, %1, %2, %0;" : "+l"(acc) : "l"(a), "l"(b));
}
__device__ __forceinline__ ull pack2(float s) {
    ull r; unsigned si = __float_as_uint(s);
    asm("mov.b64 %0, {%1, %1};" : "=l"(r) : "r"(si));
    return r;
}
__device__ __forceinline__ float dot4(float4 a, float4 b) {
    return a.x * b.x + a.y * b.y + a.z * b.z + a.w * b.w;
}

// ---- scratch + barrier (monotonic; never reset -> graph-replay safe) ----
__device__ float g_A[BSZ * RNK * DIM];     // [b][r*DIM+d]
__device__ float g_B[BSZ * RNK * DIM];     // [b][r*DIM+o], pre-scaled
__device__ unsigned g_count;               // zero-init at module load

// ============================================================
// ONE kernel, 256 blocks x 512 threads, single co-resident wave.
//  stage 0: prefetch this block's Wa/Wb slice (2 float4/thread)
//  stage 1: warps 0-7 compute gate[0..7] (LN -> 60-ReLU -> 4 -> softmax)
//  stage 2: write 1/256 slice of g_A / g_B
//  stage 3: device-wide monotonic barrier
//  stage 4: R7-proven main loop (stage A in smem, 4 rows/warp phase 1,
//           f32x2 phase 2 with coalesced STG.128)
// ============================================================
extern __shared__ float As[];   // RNK*DIM = 64 KB

__global__ __launch_bounds__(512, 2)
void lorec_kernel(const float* __restrict__ x,
                  const float* __restrict__ ctr,
                  const float* __restrict__ gamma,
                  const float* __restrict__ beta,
                  const float* __restrict__ W1,
                  const float* __restrict__ b1,
                  const float* __restrict__ W2,
                  const float* __restrict__ b2,
                  const float* __restrict__ Wa,
                  const float* __restrict__ Wb,
                  float* __restrict__ out) {
    __shared__ ull   xa2_s[ROWS_PER_BLOCK][RNK];
    __shared__ float z_s[BSZ][32];
    __shared__ float h_s[BSZ][60];
    __shared__ float gate_s[BSZ][4];

    int warp = threadIdx.x >> 5;
    int lane = threadIdx.x & 31;

    // ---- stage 0: prefetch adapter-weight slice (independent of gate) ----
    // Block covers 1024 consecutive floats of the 262144-float A+B space.
    const int TOT_A = BSZ * RNK * DIM;                 // 131072
    int i0 = blockIdx.x * 1024 + threadIdx.x;
    int i1 = i0 + 512;
    bool isA0 = i0 < TOT_A, isA1 = i1 < TOT_A;
    int ii0 = isA0 ? i0 : i0 - TOT_A;
    int ii1 = isA1 ? i1 : i1 - TOT_A;
    int j0 = ii0 & (RNK * DIM - 1), b0 = ii0 >> 14;
    int j1 = ii1 & (RNK * DIM - 1), b1v = ii1 >> 14;
    float4 w40 = __ldg((isA0 ? (const float4*)Wa : (const float4*)Wb) + j0);
    float4 w41 = __ldg((isA1 ? (const float4*)Wa : (const float4*)Wb) + j1);

    // ---- stage 1: gate MLP, warp w -> batch w ----
    if (warp < BSZ) {
        int w = warp;
        float v = ctr[w * 32 + lane];
        float m = v;
        #pragma unroll
        for (int off = 16; off; off >>= 1) m += __shfl_xor_sync(0xffffffffu, m, off);
        m *= (1.0f / 32.0f);
        float d = v - m;
        float s = d * d;
        #pragma unroll
        for (int off = 16; off; off >>= 1) s += __shfl_xor_sync(0xffffffffu, s, off);
        s *= (1.0f / 32.0f);
        z_s[w][lane] = d * rsqrtf(s + 1e-5f) * gamma[lane] + beta[lane];
        __syncwarp();

        for (int jj = lane; jj < 60; jj += 32) {
            float acc = b1[jj];
            #pragma unroll
            for (int c = 0; c < 32; c++) acc += z_s[w][c] * W1[jj * 32 + c];
            h_s[w][jj] = fmaxf(acc, 0.0f);
        }
        __syncwarp();

        if (lane == 0) {
            float g[4];
            #pragma unroll
            for (int k = 0; k < 4; k++) {
                float acc = b2[k];
                for (int jj = 0; jj < 60; jj++) acc += h_s[w][jj] * W2[k * 60 + jj];
                g[k] = acc;
            }
            float mx = fmaxf(fmaxf(g[0], g[1]), fmaxf(g[2], g[3]));
            float e0 = expf(g[0] - mx), e1 = expf(g[1] - mx);
            float e2 = expf(g[2] - mx), e3 = expf(g[3] - mx);
            float inv = 1.0f / (e0 + e1 + e2 + e3);
            gate_s[w][0] = e0 * inv;
            gate_s[w][1] = e1 * inv;
            gate_s[w][2] = e2 * inv;
            gate_s[w][3] = e3 * inv;
        }
    }
    __syncthreads();

    // ---- stage 2: write this block's A/B slice ----
    {
        float4 ga = *(const float4*)gate_s[b0];
        float4 gb = *(const float4*)gate_s[b1v];
        float v0 = dot4(ga, w40) * (isA0 ? 1.0f : SCALING);
        float v1 = dot4(gb, w41) * (isA1 ? 1.0f : SCALING);
        (isA0 ? g_A : g_B)[ii0] = v0;
        (isA1 ? g_A : g_B)[ii1] = v1;
    }
    __syncthreads();

    // ---- stage 3: device-wide monotonic barrier ----
    if (threadIdx.x == 0) {
        __threadfence();                         // publish g_A/g_B writes
        unsigned old = atomicAdd(&g_count, 1u);
        unsigned target = (old & ~(NBLOCKS - 1u)) + NBLOCKS;
        unsigned cur;
        do {
            asm volatile("ld.acquire.gpu.u32 %0, [%1];"
                         : "=r"(cur) : "l"(&g_count));
        } while ((int)(cur - target) < 0);       // wrap-safe
    }
    __syncthreads();

    // ================= main work (identical to R7) =================
    int b    = blockIdx.x >> 5;
    int row0 = (blockIdx.x & 31) * ROWS_PER_BLOCK;

    // ---- stage A[b] into smem ----
    {
        const float4* src = (const float4*)(g_A + b * RNK * DIM);
        float4* dst = (float4*)As;
        #pragma unroll
        for (int i = threadIdx.x; i < (RNK * DIM) / 4; i += 512) dst[i] = src[i];
    }
    __syncthreads();

    // ---- phase 1: warp handles 4 rows; FFMA dots vs smem A ----
    {
        const float4* xw =
            (const float4*)(x + ((size_t)b * SEQ + row0 + warp * ROWS_PER_WARP) * DIM);
        const float4* As4 = (const float4*)As;

        float acc[ROWS_PER_WARP][RNK];
        #pragma unroll
        for (int jr = 0; jr < ROWS_PER_WARP; jr++)
            #pragma unroll
            for (int r = 0; r < RNK; r++) acc[jr][r] = 0.0f;

        #pragma unroll 2
        for (int k = 0; k < 16; k++) {
            int d4 = k * 32 + lane;
            float4 xv0 = __ldcs(xw + 0 * (DIM / 4) + d4);
            float4 xv1 = __ldcs(xw + 1 * (DIM / 4) + d4);
            float4 xv2 = __ldcs(xw + 2 * (DIM / 4) + d4);
            float4 xv3 = __ldcs(xw + 3 * (DIM / 4) + d4);
            #pragma unroll
            for (int r = 0; r < RNK; r++) {
                float4 a = As4[r * 512 + d4];
                acc[0][r] += dot4(xv0, a);
                acc[1][r] += dot4(xv1, a);
                acc[2][r] += dot4(xv2, a);
                acc[3][r] += dot4(xv3, a);
            }
        }
        #pragma unroll
        for (int jr = 0; jr < ROWS_PER_WARP; jr++) {
            #pragma unroll
            for (int r = 0; r < RNK; r++) {
                float s = acc[jr][r];
                #pragma unroll
                for (int off = 16; off; off >>= 1)
                    s += __shfl_xor_sync(0xffffffffu, s, off);
                if (lane == 0) xa2_s[warp * ROWS_PER_WARP + jr][r] = pack2(s);
            }
        }
    }
    __syncthreads();

    // ---- phase 2: thread owns 4 out cols; 64 rows; f32x2 ----
    {
        const float4* Bb4 = (const float4*)(g_B + b * RNK * DIM);
        ull Br0[RNK], Br1[RNK];
        #pragma unroll
        for (int r = 0; r < RNK; r++) {
            float4 bc = __ldg(Bb4 + r * (DIM / 4) + threadIdx.x);
            ulonglong2 p = *(ulonglong2*)&bc;
            Br0[r] = p.x;
            Br1[r] = p.y;
        }

        float4* orow = (float4*)(out + ((size_t)b * SEQ + row0) * DIM) + threadIdx.x;
        #pragma unroll 4
        for (int i = 0; i < ROWS_PER_BLOCK; i++) {
            ull o0 = 0ull, o1 = 0ull;
            #pragma unroll
            for (int r = 0; r < RNK; r++) {
                ull s2 = xa2_s[i][r];
                fma2(o0, s2, Br0[r]);
                fma2(o1, s2, Br1[r]);
            }
            ulonglong2 ov; ov.x = o0; ov.y = o1;
            __stcs(orow, *(float4*)&ov);
            orow += DIM / 4;
        }
    }
}

// ============================================================
// launcher — single launch
// ============================================================
extern "C" void kernel_launch(void* const* d_in, const int* in_sizes, int n_in,
                              void* d_out, int out_size) {
    const float* x     = (const float*)d_in[0];
    const float* ctr   = (const float*)d_in[1];
    const float* gamma = (const float*)d_in[2];
    const float* beta  = (const float*)d_in[3];
    const float* W1    = (const float*)d_in[4];
    const float* b1    = (const float*)d_in[5];
    const float* W2    = (const float*)d_in[6];
    const float* b2    = (const float*)d_in[7];
    const float* Wa    = (const float*)d_in[8];
    const float* Wb    = (const float*)d_in[9];
    float* out = (float*)d_out;

    static bool attr_set = false;
    if (!attr_set) {
        cudaFuncSetAttribute(lorec_kernel,
                             cudaFuncAttributeMaxDynamicSharedMemorySize,
                             RNK * DIM * (int)sizeof(float));
        attr_set = true;
    }

    lorec_kernel<<<NBLOCKS, 512, RNK * DIM * sizeof(float)>>>(
        x, ctr, gamma, beta, W1, b1, W2, b2, Wa, Wb, out);
}

// round 9
// speedup vs baseline: 1.1695x; 1.1695x over previous
#include <cuda_runtime.h>
#include <math.h>

#define RNK 8
#define DIM 2048
#define BSZ 8
#define SEQ 2048
#define BLOCKS_PER_BATCH 37            /* 8*37 = 296 = 148 SMs * occ 2 */
#define NBLOCKS (BSZ * BLOCKS_PER_BATCH)
#define MAX_ROWS 56                    /* 13 blocks of 56 + 24 of 55 = 2048 */
#define SCALING 2.0f                   /* 16 / r */

typedef unsigned long long ull;

__device__ __forceinline__ void fma2(ull& acc, ull a, ull b) {
    asm("fma.rn.f32x2 %0, %1, %2, %0;" : "+l"(acc) : "l"(a), "l"(b));
}
__device__ __forceinline__ ull pack2(float s) {
    ull r; unsigned si = __float_as_uint(s);
    asm("mov.b64 %0, {%1, %1};" : "=l"(r) : "r"(si));
    return r;
}
__device__ __forceinline__ float dot4(float4 a, float4 b) {
    return a.x * b.x + a.y * b.y + a.z * b.z + a.w * b.w;
}

// ---- scratch ----
__device__ float g_A[BSZ * RNK * DIM];   // [b][r*DIM+d]
__device__ float g_B[BSZ * RNK * DIM];   // [b][r*DIM+o], pre-scaled by SCALING

// ============================================================
// Kernel 1: gate MLP (per-block redundant, overlapped with the hoisted
// Wa/Wb loads) + adapter build.  64 blocks x 512 threads.  (R7-proven.)
// ============================================================
__global__ __launch_bounds__(512)
void gate_ab_kernel(const float* __restrict__ ctr,
                    const float* __restrict__ gamma,
                    const float* __restrict__ beta,
                    const float* __restrict__ W1,
                    const float* __restrict__ b1,
                    const float* __restrict__ W2,
                    const float* __restrict__ b2,
                    const float* __restrict__ Wa,
                    const float* __restrict__ Wb) {
    __shared__ float z_s[BSZ][32];
    __shared__ float h_s[BSZ][60];
    __shared__ float gate_s[BSZ][4];

    int warp = threadIdx.x >> 5;
    int lane = threadIdx.x & 31;

    // hoisted big load, in flight during the gate chain
    int idx = blockIdx.x * 512 + threadIdx.x;          // [0, 32768)
    int j = idx & (RNK * DIM - 1);
    bool isA = idx < RNK * DIM;
    const float4* Wrow = isA ? (const float4*)Wa : (const float4*)Wb;
    float4 w4 = __ldg(Wrow + j);

    if (warp < BSZ) {
        int w = warp;
        float v = ctr[w * 32 + lane];
        float m = v;
        #pragma unroll
        for (int off = 16; off; off >>= 1) m += __shfl_xor_sync(0xffffffffu, m, off);
        m *= (1.0f / 32.0f);
        float d = v - m;
        float s = d * d;
        #pragma unroll
        for (int off = 16; off; off >>= 1) s += __shfl_xor_sync(0xffffffffu, s, off);
        s *= (1.0f / 32.0f);
        z_s[w][lane] = d * rsqrtf(s + 1e-5f) * gamma[lane] + beta[lane];
        __syncwarp();

        for (int jj = lane; jj < 60; jj += 32) {
            float acc = b1[jj];
            #pragma unroll
            for (int c = 0; c < 32; c++) acc += z_s[w][c] * W1[jj * 32 + c];
            h_s[w][jj] = fmaxf(acc, 0.0f);
        }
        __syncwarp();

        if (lane == 0) {
            float g[4];
            #pragma unroll
            for (int k = 0; k < 4; k++) {
                float acc = b2[k];
                for (int jj = 0; jj < 60; jj++) acc += h_s[w][jj] * W2[k * 60 + jj];
                g[k] = acc;
            }
            float mx = fmaxf(fmaxf(g[0], g[1]), fmaxf(g[2], g[3]));
            float e0 = expf(g[0] - mx), e1 = expf(g[1] - mx);
            float e2 = expf(g[2] - mx), e3 = expf(g[3] - mx);
            float inv = 1.0f / (e0 + e1 + e2 + e3);
            gate_s[w][0] = e0 * inv;
            gate_s[w][1] = e1 * inv;
            gate_s[w][2] = e2 * inv;
            gate_s[w][3] = e3 * inv;
        }
    }
    __syncthreads();

    float* dst = isA ? g_A : g_B;
    float scale = isA ? 1.0f : SCALING;
    #pragma unroll
    for (int b = 0; b < BSZ; b++) {
        float4 g4 = *(const float4*)gate_s[b];
        dst[b * RNK * DIM + j] =
            scale * (w4.x * g4.x + w4.y * g4.y + w4.z * g4.z + w4.w * g4.w);
    }
}

// ============================================================
// Kernel 2: 296 blocks (one exact co-resident wave) x 512 threads.
//   block = (batch b = bid/37, slot = bid%37) -> 55 or 56 contiguous rows,
//   never crossing a batch boundary.
//   Phase 1: warps take 3 or 4 rows (warp<rem -> 4).  3-row warps load
//   their own row 2 again as the phantom 4th row (L1-hit, discarded)
//   so the inner loop is branch-free.
//   Phase 2: thread owns 4 out cols, f32x2, runtime row loop.
// ============================================================
extern __shared__ float As[];   // RNK*DIM = 64 KB

__global__ __launch_bounds__(512, 2)
void main_kernel(const float* __restrict__ x, float* __restrict__ out) {
    __shared__ ull xa2_s[64][RNK];

    int b    = blockIdx.x / BLOCKS_PER_BATCH;
    int slot = blockIdx.x - b * BLOCKS_PER_BATCH;
    // 13 blocks of 56 rows, then 24 of 55
    int nrows   = (slot < 13) ? 56 : 55;
    int rowbase = (slot < 13) ? slot * 56 : 728 + (slot - 13) * 55;
    int rem = nrows - 48;                       // 8 or 7: warps with 4 rows

    int warp = threadIdx.x >> 5;
    int lane = threadIdx.x & 31;

    // ---- stage A[b] into smem ----
    {
        const float4* src = (const float4*)(g_A + b * RNK * DIM);
        float4* dst = (float4*)As;
        #pragma unroll
        for (int i = threadIdx.x; i < (RNK * DIM) / 4; i += 512) dst[i] = src[i];
    }
    __syncthreads();

    // ---- phase 1 ----
    {
        bool has4  = warp < rem;
        int wstart = 3 * warp + (has4 ? warp : rem);    // 3w + min(w, rem)
        const float4* xw =
            (const float4*)(x + ((size_t)b * SEQ + rowbase + wstart) * DIM);
        int off3 = (has4 ? 3 : 2) * (DIM / 4);          // phantom = own row 2
        const float4* As4 = (const float4*)As;

        float acc[4][RNK];
        #pragma unroll
        for (int jr = 0; jr < 4; jr++)
            #pragma unroll
            for (int r = 0; r < RNK; r++) acc[jr][r] = 0.0f;

        #pragma unroll 2
        for (int k = 0; k < 16; k++) {
            int d4 = k * 32 + lane;
            float4 xv0 = __ldcs(xw + 0 * (DIM / 4) + d4);
            float4 xv1 = __ldcs(xw + 1 * (DIM / 4) + d4);
            float4 xv2 = __ldcs(xw + 2 * (DIM / 4) + d4);
            float4 xv3 = __ldcs(xw + off3 + d4);
            #pragma unroll
            for (int r = 0; r < RNK; r++) {
                float4 a = As4[r * 512 + d4];
                acc[0][r] += dot4(xv0, a);
                acc[1][r] += dot4(xv1, a);
                acc[2][r] += dot4(xv2, a);
                acc[3][r] += dot4(xv3, a);
            }
        }
        #pragma unroll
        for (int jr = 0; jr < 4; jr++) {
            #pragma unroll
            for (int r = 0; r < RNK; r++) {
                float s = acc[jr][r];
                #pragma unroll
                for (int off = 16; off; off >>= 1)
                    s += __shfl_xor_sync(0xffffffffu, s, off);
                if (lane == 0 && (jr < 3 || has4))
                    xa2_s[wstart + jr][r] = pack2(s);
            }
        }
    }
    __syncthreads();

    // ---- phase 2 ----
    {
        const float4* Bb4 = (const float4*)(g_B + b * RNK * DIM);
        ull Br0[RNK], Br1[RNK];
        #pragma unroll
        for (int r = 0; r < RNK; r++) {
            float4 bc = __ldg(Bb4 + r * (DIM / 4) + threadIdx.x);
            ulonglong2 p = *(ulonglong2*)&bc;
            Br0[r] = p.x;
            Br1[r] = p.y;
        }

        float4* orow = (float4*)(out + ((size_t)b * SEQ + rowbase) * DIM)
                       + threadIdx.x;
        #pragma unroll 4
        for (int i = 0; i < nrows; i++) {
            ull o0 = 0ull, o1 = 0ull;
            #pragma unroll
            for (int r = 0; r < RNK; r++) {
                ull s2 = xa2_s[i][r];
                fma2(o0, s2, Br0[r]);
                fma2(o1, s2, Br1[r]);
            }
            ulonglong2 ov; ov.x = o0; ov.y = o1;
            __stcs(orow, *(float4*)&ov);
            orow += DIM / 4;
        }
    }
}

// ============================================================
// launcher
// ============================================================
extern "C" void kernel_launch(void* const* d_in, const int* in_sizes, int n_in,
                              void* d_out, int out_size) {
    const float* x     = (const float*)d_in[0];
    const float* ctr   = (const float*)d_in[1];
    const float* gamma = (const float*)d_in[2];
    const float* beta  = (const float*)d_in[3];
    const float* W1    = (const float*)d_in[4];
    const float* b1    = (const float*)d_in[5];
    const float* W2    = (const float*)d_in[6];
    const float* b2    = (const float*)d_in[7];
    const float* Wa    = (const float*)d_in[8];
    const float* Wb    = (const float*)d_in[9];
    float* out = (float*)d_out;

    static bool attr_set = false;
    if (!attr_set) {
        cudaFuncSetAttribute(main_kernel,
                             cudaFuncAttributeMaxDynamicSharedMemorySize,
                             RNK * DIM * (int)sizeof(float));
        attr_set = true;
    }

    gate_ab_kernel<<<(2 * RNK * DIM) / 512, 512>>>(ctr, gamma, beta,
                                                   W1, b1, W2, b2, Wa, Wb);
    main_kernel<<<NBLOCKS, 512, RNK * DIM * sizeof(float)>>>(x, out);
}